// round 14
// baseline (speedup 1.0000x reference)
#include <cuda_runtime.h>
#include <cuda_fp16.h>
#include <cstdint>

constexpr int BATCH = 8192;
constexpr int HDIM  = 512;
constexpr int NBIG  = 8192;       // H*K columns of GEMM2
constexpr int NTILES_N = 64;      // NBIG / 128

// fp16 operands (device globals; selected device-side only — GB300 ATS trap)
__device__ __half g_A1[BATCH * HDIM];     // (v_passive - 0.5)
__device__ __half g_W1T[HDIM * HDIM];     // W1 transposed: [n][k]
__device__ __half g_W2T[NBIG * HDIM];     // W2 transposed: [n][k]
__device__ __half g_h[BATCH * HDIM];      // tanh(layer1) as fp16
__device__ float  g_partial[BATCH * NTILES_N];

__device__ __forceinline__ float fast_tanh(float x) {
    float y; asm("tanh.approx.f32 %0, %1;" : "=f"(y) : "f"(x)); return y;
}
// e^u for u in [-1,1], degree-8 Taylor (rel err ~7e-6), pure FMA pipe
__device__ __forceinline__ float exp_poly(float u) {
    float r = 2.48015873e-05f;
    r = fmaf(r, u, 1.98412698e-04f); r = fmaf(r, u, 1.38888889e-03f);
    r = fmaf(r, u, 8.33333333e-03f); r = fmaf(r, u, 4.16666667e-02f);
    r = fmaf(r, u, 1.66666667e-01f); r = fmaf(r, u, 0.5f);
    r = fmaf(r, u, 1.0f); r = fmaf(r, u, 1.0f);
    return r;
}

__device__ __forceinline__ void mma_fp16(float* c, const uint32_t* a, const uint32_t* b) {
    asm volatile(
        "mma.sync.aligned.m16n8k16.row.col.f32.f16.f16.f32 "
        "{%0,%1,%2,%3}, {%4,%5,%6,%7}, {%8,%9}, {%0,%1,%2,%3};\n"
        : "+f"(c[0]), "+f"(c[1]), "+f"(c[2]), "+f"(c[3])
        : "r"(a[0]), "r"(a[1]), "r"(a[2]), "r"(a[3]), "r"(b[0]), "r"(b[1]));
}
__device__ __forceinline__ void ldsm_x4(uint32_t* r, uint32_t addr) {
    asm volatile("ldmatrix.sync.aligned.m8n8.x4.shared.b16 {%0,%1,%2,%3}, [%4];"
                 : "=r"(r[0]), "=r"(r[1]), "=r"(r[2]), "=r"(r[3]) : "r"(addr));
}

#define CPA16(dst, src) \
    asm volatile("cp.async.cg.shared.global [%0], [%1], 16;\n" :: "r"(dst), "l"(src))

// smem per stage (halves): A[128][40] then B[128][40]. Row stride 40 halves =
// 20 words; 8 consecutive rows start at words {0,20,8,28,16,4,24,12} mod 32
// -> every ldmatrix 8-lane phase tiles all 32 banks.
constexpr int A_STR    = 40;
constexpr int A_STAGE  = 128 * A_STR;        // 5120 halves
constexpr int STAGE_H  = 2 * A_STAGE;        // 10240 halves (A then B)
constexpr int NSTAGE   = 3;
constexpr int SMEM_BYTES = NSTAGE * STAGE_H * 2;   // 61440 B (dynamic)

// ---------------------------------------------------------------------------
// fp16 tensor-core GEMM (128x128 tile, BK=32, 256 thr, 8 warps @ 32x64 each),
// 3-stage cp.async pipeline, ONE __syncthreads per mainloop iteration.
// MODE 0: C = tanh(g_A1 @ g_W1T^T + b1) -> g_h (fp16)
// MODE 1: fused spline epilogue on tanh(g_h @ g_W2T^T + b2) -> out + g_partial
// ---------------------------------------------------------------------------
template <int MODE>
__global__ __launch_bounds__(256, 2)
void gemm_fp16(const float* __restrict__ bias, const float* __restrict__ v_in,
               float* __restrict__ outp) {
    extern __shared__ __align__(16) __half sm[];
    __shared__ float partial2[256];

    const __half* __restrict__ Ag = (MODE == 0) ? g_A1 : g_h;
    const __half* __restrict__ Bg = (MODE == 0) ? g_W1T : g_W2T;

    const int t = threadIdx.x;
    const int wid = t >> 5, lane = t & 31;
    const int warp_m = wid >> 1, warp_n = wid & 1;   // 4 x 2
    const int gr = lane >> 2, tc = lane & 3;
    const int m0 = blockIdx.y * 128, n0 = blockIdx.x * 128;

    const uint32_t sbase = (uint32_t)__cvta_generic_to_shared(sm);

    // per-lane ldmatrix source offsets (halves), within a stage
    const uint32_t a_lm = (uint32_t)((warp_m * 32 + (lane & 7) + ((lane >> 3) & 1) * 8) * A_STR
                                     + (lane >> 4) * 8);
    const uint32_t b_lm = (uint32_t)(A_STAGE
                                     + (warp_n * 64 + (lane & 7) + (lane >> 4) * 8) * A_STR
                                     + ((lane >> 3) & 1) * 8);

    float acc[2][8][4];
#pragma unroll
    for (int mt = 0; mt < 2; mt++)
#pragma unroll
        for (int nt = 0; nt < 8; nt++)
#pragma unroll
            for (int r = 0; r < 4; r++) acc[mt][nt][r] = 0.f;

    const int p_row = t >> 1, p_kq = (t & 1) * 16;
    auto prefetch = [&](int it) {
        const int s = it % NSTAGE;
        const int k0 = it * 32;
        const __half* asrc = Ag + (size_t)(m0 + p_row) * HDIM + k0 + p_kq;
        const __half* bsrc = Bg + (size_t)(n0 + p_row) * HDIM + k0 + p_kq;
        const uint32_t adst = sbase + (uint32_t)(s * STAGE_H + p_row * A_STR + p_kq) * 2u;
        const uint32_t bdst = sbase + (uint32_t)(s * STAGE_H + A_STAGE + p_row * A_STR + p_kq) * 2u;
        CPA16(adst, asrc);
        CPA16(adst + 16, asrc + 8);
        CPA16(bdst, bsrc);
        CPA16(bdst + 16, bsrc + 8);
        asm volatile("cp.async.commit_group;\n");
    };

    prefetch(0);
    prefetch(1);

    for (int it = 0; it < 16; ++it) {
        // groups committed so far: 0..it+1; need group `it` complete.
        if (it < 15) asm volatile("cp.async.wait_group 1;\n");
        else         asm volatile("cp.async.wait_group 0;\n");
        __syncthreads();                      // ONE barrier per iteration
        if (it < 14) prefetch(it + 2);        // writes stage (it+2)%3 — safe:
                                              // its readers (iter it-1) are past
                                              // the barrier above.
        const uint32_t stg = sbase + (uint32_t)((it % NSTAGE) * STAGE_H) * 2u;
#pragma unroll
        for (int ks = 0; ks < 2; ks++) {
            uint32_t af[2][4], bf[8][2];
#pragma unroll
            for (int mt = 0; mt < 2; mt++)
                ldsm_x4(af[mt], stg + (a_lm + mt * 16 * A_STR + ks * 16) * 2u);
#pragma unroll
            for (int ntp = 0; ntp < 4; ntp++) {
                uint32_t br[4];
                ldsm_x4(br, stg + (b_lm + ntp * 16 * A_STR + ks * 16) * 2u);
                bf[2 * ntp][0] = br[0]; bf[2 * ntp][1] = br[1];
                bf[2 * ntp + 1][0] = br[2]; bf[2 * ntp + 1][1] = br[3];
            }
#pragma unroll
            for (int mt = 0; mt < 2; mt++)
#pragma unroll
                for (int nt = 0; nt < 8; nt++)
                    mma_fp16(acc[mt][nt], af[mt], bf[nt]);
        }
    }
    __syncthreads();   // stage reads done before epilogue overlays smem

    if (MODE == 0) {
        // tanh(acc + bias) -> g_h as fp16 (half2 stores)
#pragma unroll
        for (int mt = 0; mt < 2; mt++) {
            const int R = m0 + warp_m * 32 + mt * 16 + gr;
#pragma unroll
            for (int nt = 0; nt < 8; nt++) {
                const int C = n0 + warp_n * 64 + nt * 8 + tc * 2;
                const float b0 = bias[C], b1 = bias[C + 1];
                __half2 v0 = __floats2half2_rn(fast_tanh(acc[mt][nt][0] + b0),
                                               fast_tanh(acc[mt][nt][1] + b1));
                __half2 v1 = __floats2half2_rn(fast_tanh(acc[mt][nt][2] + b0),
                                               fast_tanh(acc[mt][nt][3] + b1));
                *(__half2*)&g_h[(size_t)R * HDIM + C] = v0;
                *(__half2*)&g_h[(size_t)(R + 8) * HDIM + C] = v1;
            }
        }
        return;
    }

    // ---- MODE 1: spline epilogue, two 64-row phases staged through smem ----
    float* U = (float*)sm;  // 64 x 132 floats = 33.8 KB (fits in dynamic smem)
    const int row = t & 63;
    const int gq = (t >> 6) * 2;   // 4 thread-groups x 2 h-groups = 8

#pragma unroll
    for (int p = 0; p < 2; p++) {
        __syncthreads();
        if ((warp_m >> 1) == p) {   // warps 2p, 2p+1 own rows [p*64, p*64+64)
#pragma unroll
            for (int mt = 0; mt < 2; mt++) {
                const int rl = (warp_m & 1) * 32 + mt * 16 + gr;
#pragma unroll
                for (int nt = 0; nt < 8; nt++) {
                    const int cl = warp_n * 64 + nt * 8 + tc * 2;
                    const float b0 = bias[n0 + cl], b1 = bias[n0 + cl + 1];
                    U[rl * 132 + cl] = fast_tanh(acc[mt][nt][0] + b0);
                    U[rl * 132 + cl + 1] = fast_tanh(acc[mt][nt][1] + b1);
                    U[(rl + 8) * 132 + cl] = fast_tanh(acc[mt][nt][2] + b0);
                    U[(rl + 8) * 132 + cl + 1] = fast_tanh(acc[mt][nt][3] + b1);
                }
            }
        }
        __syncthreads();

        const int grow = m0 + p * 64 + row;
        const int hbase = (n0 >> 4) + gq;
        float2 av = *(const float2*)&v_in[(size_t)grow * 1024 + 512 + hbase];
        float2 ov;
        float nlp = 0.f;
#pragma unroll
        for (int gg = 0; gg < 2; gg++) {
            const float a = (&av.x)[gg];
            const float tk = a * 16.0f;  // exact
            int k = (int)ceilf(tk) - 1;
            k = k < 0 ? 0 : (k > 15 ? 15 : k);
            const float4* up = (const float4*)&U[row * 132 + (gq + gg) * 16];
            float Z = 0.f, prefix = 0.f, sk = 0.f, uk = 0.f;
#pragma unroll
            for (int j4 = 0; j4 < 4; j4++) {
                float4 u4 = up[j4];
#pragma unroll
                for (int jj = 0; jj < 4; jj++) {
                    const int j = j4 * 4 + jj;
                    const float u = (&u4.x)[jj];
                    const float s = exp_poly(u);
                    Z += s;
                    prefix += (j < k) ? s : 0.f;
                    if (j == k) { sk = s; uk = u; }
                }
            }
            const float alpha = tk - (float)k;
            (&ov.x)[gg] = __fdividef(fmaf(alpha, sk, prefix), Z);
            nlp += __logf(Z) - uk;  // = -log p_k
        }
        *(float2*)&outp[(size_t)grow * 1024 + 512 + hbase] = ov;
        partial2[t] = nlp;
        __syncthreads();
        if (t < 64)
            g_partial[(size_t)(m0 + p * 64 + t) * NTILES_N + blockIdx.x] =
                partial2[t] + partial2[t + 64] + partial2[t + 128] + partial2[t + 192];
    }
}

// ---------------------------------------------------------------------------
// Prep kernels (destinations selected device-side)
// ---------------------------------------------------------------------------
// Fused: copy v_passive -> out[:, :512] AND write (v_passive - 0.5) as fp16
__global__ void k_prep_A(const float* __restrict__ v_in, float* __restrict__ out) {
    int i = blockIdx.x * 256 + threadIdx.x;  // over BATCH*128 float4
    int r = i >> 7, c4 = i & 127;
    float4 v = ((const float4*)v_in)[(size_t)r * 256 + c4];
    ((float4*)out)[(size_t)r * 256 + c4] = v;
    __half2 h0 = __floats2half2_rn(v.x - 0.5f, v.y - 0.5f);
    __half2 h1 = __floats2half2_rn(v.z - 0.5f, v.w - 0.5f);
    uint2 pk = make_uint2(*(uint32_t*)&h0, *(uint32_t*)&h1);
    ((uint2*)g_A1)[(size_t)r * 128 + c4] = pk;
}

// Tiled transpose to fp16: dst[n][k] = in[k][n]. WHICH selects destination.
template <int WHICH, int NCOLS>
__global__ void k_prep_WT(const float* __restrict__ in) {
    __half* __restrict__ outT = (WHICH == 0) ? g_W1T : g_W2T;
    __shared__ float tile[32][33];
    const int tx = threadIdx.x, ty = threadIdx.y;  // 32 x 8
    const int n0 = blockIdx.x * 32, k0 = blockIdx.y * 32;
#pragma unroll
    for (int i = 0; i < 4; i++)
        tile[ty + i * 8][tx] = in[(size_t)(k0 + ty + i * 8) * NCOLS + n0 + tx];
    __syncthreads();
#pragma unroll
    for (int i = 0; i < 4; i++)
        outT[(size_t)(n0 + ty + i * 8) * HDIM + k0 + tx] =
            __float2half_rn(tile[tx][ty + i * 8]);
}

__global__ void k_reduce(const float* __restrict__ log_density,
                         float* __restrict__ out, int ld_offset) {
    int r = blockIdx.x * 256 + threadIdx.x;
    if (r >= BATCH) return;
    float s = log_density[r];
    const float4* p4 = (const float4*)&g_partial[(size_t)r * NTILES_N];
#pragma unroll
    for (int i = 0; i < NTILES_N / 4; i++) {
        float4 v = p4[i];
        s += v.x + v.y + v.z + v.w;
    }
    out[ld_offset + r] = s;
}

// ---------------------------------------------------------------------------
extern "C" void kernel_launch(void* const* d_in, const int* in_sizes, int n_in,
                              void* d_out, int out_size) {
    const float* v_in        = (const float*)d_in[0];
    const float* log_density = (const float*)d_in[1];
    const float* W1          = (const float*)d_in[2];
    const float* b1          = (const float*)d_in[3];
    const float* W2          = (const float*)d_in[4];
    const float* b2          = (const float*)d_in[5];
    float* out = (float*)d_out;
    const int ld_offset = out_size - BATCH;

    static bool attr_done = false;
    if (!attr_done) {
        cudaFuncSetAttribute(gemm_fp16<0>, cudaFuncAttributeMaxDynamicSharedMemorySize, SMEM_BYTES);
        cudaFuncSetAttribute(gemm_fp16<1>, cudaFuncAttributeMaxDynamicSharedMemorySize, SMEM_BYTES);
        attr_done = true;
    }

    k_prep_A<<<BATCH * 128 / 256, 256>>>(v_in, out);
    k_prep_WT<0, HDIM><<<dim3(HDIM / 32, HDIM / 32), dim3(32, 8)>>>(W1);
    k_prep_WT<1, NBIG><<<dim3(NBIG / 32, HDIM / 32), dim3(32, 8)>>>(W2);
    gemm_fp16<0><<<dim3(HDIM / 128, BATCH / 128), 256, SMEM_BYTES>>>(b1, v_in, out);
    gemm_fp16<1><<<dim3(NBIG / 128, BATCH / 128), 256, SMEM_BYTES>>>(b2, v_in, out);
    k_reduce<<<BATCH / 256, 256>>>(log_density, out, ld_offset);
}

// round 15
// speedup vs baseline: 1.1540x; 1.1540x over previous
#include <cuda_runtime.h>
#include <cuda_fp16.h>
#include <cstdint>

constexpr int BATCH = 8192;
constexpr int HDIM  = 512;
constexpr int NBIG  = 8192;       // H*K columns of GEMM2
constexpr int NTILES_N = 64;      // NBIG / 128

// fp16 operands (device globals; selected device-side only — GB300 ATS trap)
__device__ __half g_A1[BATCH * HDIM];     // (v_passive - 0.5)
__device__ __half g_W1T[HDIM * HDIM];     // W1 transposed: [n][k]
__device__ __half g_W2T[NBIG * HDIM];     // W2 transposed: [n][k]
__device__ __half g_h[BATCH * HDIM];      // tanh(layer1) as fp16
__device__ float  g_partial[BATCH * NTILES_N];

__device__ __forceinline__ float fast_tanh(float x) {
    float y; asm("tanh.approx.f32 %0, %1;" : "=f"(y) : "f"(x)); return y;
}
// e^u for u in [-1,1], degree-8 Taylor (rel err ~7e-6), pure FMA pipe
__device__ __forceinline__ float exp_poly(float u) {
    float r = 2.48015873e-05f;
    r = fmaf(r, u, 1.98412698e-04f); r = fmaf(r, u, 1.38888889e-03f);
    r = fmaf(r, u, 8.33333333e-03f); r = fmaf(r, u, 4.16666667e-02f);
    r = fmaf(r, u, 1.66666667e-01f); r = fmaf(r, u, 0.5f);
    r = fmaf(r, u, 1.0f); r = fmaf(r, u, 1.0f);
    return r;
}

__device__ __forceinline__ void mma_fp16(float* c, const uint32_t* a, const uint32_t* b) {
    asm volatile(
        "mma.sync.aligned.m16n8k16.row.col.f32.f16.f16.f32 "
        "{%0,%1,%2,%3}, {%4,%5,%6,%7}, {%8,%9}, {%0,%1,%2,%3};\n"
        : "+f"(c[0]), "+f"(c[1]), "+f"(c[2]), "+f"(c[3])
        : "r"(a[0]), "r"(a[1]), "r"(a[2]), "r"(a[3]), "r"(b[0]), "r"(b[1]));
}
__device__ __forceinline__ void ldsm_x4(uint32_t* r, uint32_t addr) {
    asm volatile("ldmatrix.sync.aligned.m8n8.x4.shared.b16 {%0,%1,%2,%3}, [%4];"
                 : "=r"(r[0]), "=r"(r[1]), "=r"(r[2]), "=r"(r[3]) : "r"(addr));
}

#define CPA16(dst, src) \
    asm volatile("cp.async.cg.shared.global [%0], [%1], 16;\n" :: "r"(dst), "l"(src))

// Row stride 40 halves = 20 words; 8 consecutive rows start at words
// {0,20,8,28,16,4,24,12} mod 32 -> every ldmatrix 8-lane phase tiles all banks.
constexpr int A_STR = 40;

// ---------------------------------------------------------------------------
// fp16 tensor-core GEMM, BK=32, round-13 proven mainloop (2-stage, (it&1)).
// MODE 0: 128x128 tile, 256 thr (8 warps 4x2 of 32x64), 2 CTAs/SM.
//         C = tanh(g_A1 @ g_W1T^T + b1) -> g_h (fp16)
// MODE 1: 256x128 tile, 512 thr (16 warps 8x2 of 32x64), 1 CTA/SM.
//         fused spline epilogue on tanh(g_h @ g_W2T^T + b2) -> out + g_partial
// ---------------------------------------------------------------------------
template <int MODE>
__global__ __launch_bounds__(MODE == 0 ? 256 : 512, MODE == 0 ? 2 : 1)
void gemm_fp16(const float* __restrict__ bias, const float* __restrict__ v_in,
               float* __restrict__ outp) {
    constexpr int TM   = (MODE == 0) ? 128 : 256;
    constexpr int NTHR = (MODE == 0) ? 256 : 512;
    constexpr int A_STAGE = TM * A_STR;              // halves
    constexpr int STG     = (TM + 128) * A_STR;      // halves per stage
    constexpr int CHUNKS  = (TM + 128) * 4 / NTHR;   // 16B chunks per thread

    extern __shared__ __align__(16) __half sm[];
    __shared__ float partial2[512];

    const __half* __restrict__ Ag = (MODE == 0) ? g_A1 : g_h;
    const __half* __restrict__ Bg = (MODE == 0) ? g_W1T : g_W2T;

    const int t = threadIdx.x;
    const int wid = t >> 5, lane = t & 31;
    const int warp_m = wid >> 1, warp_n = wid & 1;
    const int gr = lane >> 2, tc = lane & 3;
    const int m0 = blockIdx.y * TM, n0 = blockIdx.x * 128;

    const uint32_t sbase = (uint32_t)__cvta_generic_to_shared(sm);

    // per-lane ldmatrix source offsets (halves), within a stage
    const uint32_t a_lm = (uint32_t)((warp_m * 32 + (lane & 7) + ((lane >> 3) & 1) * 8) * A_STR
                                     + (lane >> 4) * 8);
    const uint32_t b_lm = (uint32_t)(A_STAGE
                                     + (warp_n * 64 + (lane & 7) + (lane >> 4) * 8) * A_STR
                                     + ((lane >> 3) & 1) * 8);

    float acc[2][8][4];
#pragma unroll
    for (int mt = 0; mt < 2; mt++)
#pragma unroll
        for (int nt = 0; nt < 8; nt++)
#pragma unroll
            for (int r = 0; r < 4; r++) acc[mt][nt][r] = 0.f;

    auto prefetch = [&](int it, int buf) {
        const int k0 = it * 32;
#pragma unroll
        for (int cc = 0; cc < CHUNKS; cc++) {
            const int c = t + cc * NTHR;
            const int row = c >> 2, q = c & 3;       // q*8 halves = q*16 bytes
            const __half* src = (row < TM)
                ? Ag + (size_t)(m0 + row) * HDIM + k0 + q * 8
                : Bg + (size_t)(n0 + row - TM) * HDIM + k0 + q * 8;
            const uint32_t dst = sbase + (uint32_t)(buf * STG + row * A_STR + q * 8) * 2u;
            CPA16(dst, src);
        }
        asm volatile("cp.async.commit_group;\n");
    };

    prefetch(0, 0);

    for (int it = 0; it < 16; ++it) {
        if (it < 15) prefetch(it + 1, (it + 1) & 1);
        else asm volatile("cp.async.commit_group;\n");
        asm volatile("cp.async.wait_group 1;\n");
        __syncthreads();

        const uint32_t stg = sbase + (uint32_t)((it & 1) * STG) * 2u;
#pragma unroll
        for (int ks = 0; ks < 2; ks++) {
            uint32_t af[2][4], bf[8][2];
#pragma unroll
            for (int mt = 0; mt < 2; mt++)
                ldsm_x4(af[mt], stg + (a_lm + mt * 16 * A_STR + ks * 16) * 2u);
#pragma unroll
            for (int ntp = 0; ntp < 4; ntp++) {
                uint32_t br[4];
                ldsm_x4(br, stg + (b_lm + ntp * 16 * A_STR + ks * 16) * 2u);
                bf[2 * ntp][0] = br[0]; bf[2 * ntp][1] = br[1];
                bf[2 * ntp + 1][0] = br[2]; bf[2 * ntp + 1][1] = br[3];
            }
#pragma unroll
            for (int mt = 0; mt < 2; mt++)
#pragma unroll
                for (int nt = 0; nt < 8; nt++)
                    mma_fp16(acc[mt][nt], af[mt], bf[nt]);
        }
        __syncthreads();
    }

    if (MODE == 0) {
        // tanh(acc + bias) -> g_h as fp16 (half2 stores)
#pragma unroll
        for (int mt = 0; mt < 2; mt++) {
            const int R = m0 + warp_m * 32 + mt * 16 + gr;
#pragma unroll
            for (int nt = 0; nt < 8; nt++) {
                const int C = n0 + warp_n * 64 + nt * 8 + tc * 2;
                const float b0 = bias[C], b1 = bias[C + 1];
                __half2 v0 = __floats2half2_rn(fast_tanh(acc[mt][nt][0] + b0),
                                               fast_tanh(acc[mt][nt][1] + b1));
                __half2 v1 = __floats2half2_rn(fast_tanh(acc[mt][nt][2] + b0),
                                               fast_tanh(acc[mt][nt][3] + b1));
                *(__half2*)&g_h[(size_t)R * HDIM + C] = v0;
                *(__half2*)&g_h[(size_t)(R + 8) * HDIM + C] = v1;
            }
        }
        return;
    }

    // ---- MODE 1: spline epilogue, four 64-row phases staged through smem ----
    float* U = (float*)sm;  // 64 x 132 floats = 33.8 KB (fits in dynamic smem)
    const int row = t & 63;
    const int g   = t >> 6;   // 8 thread-groups x 1 h-group each

#pragma unroll
    for (int p = 0; p < 4; p++) {
        __syncthreads();
        if ((warp_m >> 1) == p) {   // warps 2p, 2p+1 own rows [p*64, p*64+64)
#pragma unroll
            for (int mt = 0; mt < 2; mt++) {
                const int rl = (warp_m & 1) * 32 + mt * 16 + gr;
#pragma unroll
                for (int nt = 0; nt < 8; nt++) {
                    const int cl = warp_n * 64 + nt * 8 + tc * 2;
                    const float b0 = bias[n0 + cl], b1 = bias[n0 + cl + 1];
                    U[rl * 132 + cl] = fast_tanh(acc[mt][nt][0] + b0);
                    U[rl * 132 + cl + 1] = fast_tanh(acc[mt][nt][1] + b1);
                    U[(rl + 8) * 132 + cl] = fast_tanh(acc[mt][nt][2] + b0);
                    U[(rl + 8) * 132 + cl + 1] = fast_tanh(acc[mt][nt][3] + b1);
                }
            }
        }
        __syncthreads();

        const int grow = m0 + p * 64 + row;
        const int hidx = (n0 >> 4) + g;
        const float a = v_in[(size_t)grow * 1024 + 512 + hidx];
        const float tk = a * 16.0f;  // exact
        int k = (int)ceilf(tk) - 1;
        k = k < 0 ? 0 : (k > 15 ? 15 : k);
        const float4* up = (const float4*)&U[row * 132 + g * 16];
        float Z = 0.f, prefix = 0.f, sk = 0.f, uk = 0.f;
#pragma unroll
        for (int j4 = 0; j4 < 4; j4++) {
            float4 u4 = up[j4];
#pragma unroll
            for (int jj = 0; jj < 4; jj++) {
                const int j = j4 * 4 + jj;
                const float u = (&u4.x)[jj];
                const float s = exp_poly(u);
                Z += s;
                prefix += (j < k) ? s : 0.f;
                if (j == k) { sk = s; uk = u; }
            }
        }
        const float alpha = tk - (float)k;
        outp[(size_t)grow * 1024 + 512 + hidx] = __fdividef(fmaf(alpha, sk, prefix), Z);
        partial2[t] = __logf(Z) - uk;   // = -log p_k
        __syncthreads();
        if (t < 64) {
            float s = 0.f;
#pragma unroll
            for (int j = 0; j < 8; j++) s += partial2[t + 64 * j];
            g_partial[(size_t)(m0 + p * 64 + t) * NTILES_N + blockIdx.x] = s;
        }
    }
}

// ---------------------------------------------------------------------------
// Prep kernels (destinations selected device-side)
// ---------------------------------------------------------------------------
// Fused: copy v_passive -> out[:, :512] AND write (v_passive - 0.5) as fp16
__global__ void k_prep_A(const float* __restrict__ v_in, float* __restrict__ out) {
    int i = blockIdx.x * 256 + threadIdx.x;  // over BATCH*128 float4
    int r = i >> 7, c4 = i & 127;
    float4 v = ((const float4*)v_in)[(size_t)r * 256 + c4];
    ((float4*)out)[(size_t)r * 256 + c4] = v;
    __half2 h0 = __floats2half2_rn(v.x - 0.5f, v.y - 0.5f);
    __half2 h1 = __floats2half2_rn(v.z - 0.5f, v.w - 0.5f);
    uint2 pk = make_uint2(*(uint32_t*)&h0, *(uint32_t*)&h1);
    ((uint2*)g_A1)[(size_t)r * 128 + c4] = pk;
}

// Tiled transpose to fp16: dst[n][k] = in[k][n]. WHICH selects destination.
template <int WHICH, int NCOLS>
__global__ void k_prep_WT(const float* __restrict__ in) {
    __half* __restrict__ outT = (WHICH == 0) ? g_W1T : g_W2T;
    __shared__ float tile[32][33];
    const int tx = threadIdx.x, ty = threadIdx.y;  // 32 x 8
    const int n0 = blockIdx.x * 32, k0 = blockIdx.y * 32;
#pragma unroll
    for (int i = 0; i < 4; i++)
        tile[ty + i * 8][tx] = in[(size_t)(k0 + ty + i * 8) * NCOLS + n0 + tx];
    __syncthreads();
#pragma unroll
    for (int i = 0; i < 4; i++)
        outT[(size_t)(n0 + ty + i * 8) * HDIM + k0 + tx] =
            __float2half_rn(tile[tx][ty + i * 8]);
}

// 2 threads per row + shfl combine
__global__ void k_reduce(const float* __restrict__ log_density,
                         float* __restrict__ out, int ld_offset) {
    int i = blockIdx.x * 256 + threadIdx.x;
    int r = i >> 1, h = i & 1;
    float s = 0.f;
    const float4* p4 = (const float4*)&g_partial[(size_t)r * NTILES_N + h * 32];
#pragma unroll
    for (int j = 0; j < 8; j++) {
        float4 v = p4[j];
        s += v.x + v.y + v.z + v.w;
    }
    s += __shfl_xor_sync(0xffffffffu, s, 1);
    if (!h) out[ld_offset + r] = s + log_density[r];
}

// ---------------------------------------------------------------------------
extern "C" void kernel_launch(void* const* d_in, const int* in_sizes, int n_in,
                              void* d_out, int out_size) {
    const float* v_in        = (const float*)d_in[0];
    const float* log_density = (const float*)d_in[1];
    const float* W1          = (const float*)d_in[2];
    const float* b1          = (const float*)d_in[3];
    const float* W2          = (const float*)d_in[4];
    const float* b2          = (const float*)d_in[5];
    float* out = (float*)d_out;
    const int ld_offset = out_size - BATCH;

    constexpr int SMEM0 = (128 + 128) * A_STR * 2 * 2;   // 40960 B
    constexpr int SMEM1 = (256 + 128) * A_STR * 2 * 2;   // 61440 B

    static bool attr_done = false;
    if (!attr_done) {
        cudaFuncSetAttribute(gemm_fp16<0>, cudaFuncAttributeMaxDynamicSharedMemorySize, SMEM0);
        cudaFuncSetAttribute(gemm_fp16<1>, cudaFuncAttributeMaxDynamicSharedMemorySize, SMEM1);
        cudaFuncSetAttribute(gemm_fp16<0>, cudaFuncAttributePreferredSharedMemoryCarveout,
                             cudaSharedmemCarveoutMaxShared);
        cudaFuncSetAttribute(gemm_fp16<1>, cudaFuncAttributePreferredSharedMemoryCarveout,
                             cudaSharedmemCarveoutMaxShared);
        attr_done = true;
    }

    k_prep_A<<<BATCH * 128 / 256, 256>>>(v_in, out);
    k_prep_WT<0, HDIM><<<dim3(HDIM / 32, HDIM / 32), dim3(32, 8)>>>(W1);
    k_prep_WT<1, NBIG><<<dim3(NBIG / 32, HDIM / 32), dim3(32, 8)>>>(W2);
    gemm_fp16<0><<<dim3(HDIM / 128, BATCH / 128), 256, SMEM0>>>(b1, v_in, out);
    gemm_fp16<1><<<dim3(NBIG / 128, BATCH / 256), 512, SMEM1>>>(b2, v_in, out);
    k_reduce<<<BATCH * 2 / 256, 256>>>(log_density, out, ld_offset);
}

// round 16
// speedup vs baseline: 1.6668x; 1.4444x over previous
#include <cuda_runtime.h>
#include <cuda_fp16.h>
#include <cstdint>

constexpr int BATCH = 8192;
constexpr int HDIM  = 512;
constexpr int NBIG  = 8192;       // H*K columns of GEMM2
constexpr int NTILES_N = 64;      // NBIG / 128

// fp16 operands (device globals; selected device-side only — GB300 ATS trap)
__device__ __half g_A1[BATCH * HDIM];     // (v_passive - 0.5)
__device__ __half g_W1T[HDIM * HDIM];     // W1 transposed: [n][k]
__device__ __half g_W2T[NBIG * HDIM];     // W2 transposed: [n][k]
__device__ __half g_h[BATCH * HDIM];      // tanh(layer1) as fp16
__device__ float  g_partial[BATCH * NTILES_N];

__device__ __forceinline__ float fast_tanh(float x) {
    float y; asm("tanh.approx.f32 %0, %1;" : "=f"(y) : "f"(x)); return y;
}
// e^u for u in [-1,1], degree-8 Taylor (rel err ~7e-6), pure FMA pipe
__device__ __forceinline__ float exp_poly(float u) {
    float r = 2.48015873e-05f;
    r = fmaf(r, u, 1.98412698e-04f); r = fmaf(r, u, 1.38888889e-03f);
    r = fmaf(r, u, 8.33333333e-03f); r = fmaf(r, u, 4.16666667e-02f);
    r = fmaf(r, u, 1.66666667e-01f); r = fmaf(r, u, 0.5f);
    r = fmaf(r, u, 1.0f); r = fmaf(r, u, 1.0f);
    return r;
}

__device__ __forceinline__ void mma_fp16(float* c, const uint32_t* a, const uint32_t* b) {
    asm volatile(
        "mma.sync.aligned.m16n8k16.row.col.f32.f16.f16.f32 "
        "{%0,%1,%2,%3}, {%4,%5,%6,%7}, {%8,%9}, {%0,%1,%2,%3};\n"
        : "+f"(c[0]), "+f"(c[1]), "+f"(c[2]), "+f"(c[3])
        : "r"(a[0]), "r"(a[1]), "r"(a[2]), "r"(a[3]), "r"(b[0]), "r"(b[1]));
}
__device__ __forceinline__ void ldsm_x4(uint32_t* r, uint32_t addr) {
    asm volatile("ldmatrix.sync.aligned.m8n8.x4.shared.b16 {%0,%1,%2,%3}, [%4];"
                 : "=r"(r[0]), "=r"(r[1]), "=r"(r[2]), "=r"(r[3]) : "r"(addr));
}

#define CPA16(dst, src) \
    asm volatile("cp.async.cg.shared.global [%0], [%1], 16;\n" :: "r"(dst), "l"(src))

// BK=64: row stride 72 halves = 36 words = 144 B (16B-aligned).
// 8 consecutive rows start at words {0,4,8,12,16,20,24,28} mod 32, each row
// read is 4 consecutive words -> every ldmatrix 8-lane phase tiles all 32
// banks exactly once (conflict-free). k offsets shift by 8 words, still a
// permutation of banks.
constexpr int A_STR    = 72;
constexpr int A_STAGE  = 128 * A_STR;        // 9216 halves
constexpr int STG      = 256 * A_STR;        // 18432 halves per stage (A then B)
constexpr int SMEM_BYTES = 2 * STG * 2;      // 73728 B (dynamic, 2 stages)

// ---------------------------------------------------------------------------
// fp16 tensor-core GEMM (128x128 tile, BK=64, 256 thr, 8 warps @ 32x64 each),
// 2-stage cp.async pipeline (round-13 proven structure, halved barrier count).
// MODE 0: C = tanh(g_A1 @ g_W1T^T + b1) -> g_h (fp16)
// MODE 1: fused spline epilogue on tanh(g_h @ g_W2T^T + b2) -> out + g_partial
// ---------------------------------------------------------------------------
template <int MODE>
__global__ __launch_bounds__(256, 2)
void gemm_fp16(const float* __restrict__ bias, const float* __restrict__ v_in,
               float* __restrict__ outp) {
    extern __shared__ __align__(16) __half sm[];
    __shared__ float partial2[256];

    const __half* __restrict__ Ag = (MODE == 0) ? g_A1 : g_h;
    const __half* __restrict__ Bg = (MODE == 0) ? g_W1T : g_W2T;

    const int t = threadIdx.x;
    const int wid = t >> 5, lane = t & 31;
    const int warp_m = wid >> 1, warp_n = wid & 1;   // 4 x 2
    const int gr = lane >> 2, tc = lane & 3;
    const int m0 = blockIdx.y * 128, n0 = blockIdx.x * 128;

    const uint32_t sbase = (uint32_t)__cvta_generic_to_shared(sm);

    // per-lane ldmatrix source offsets (halves), within a stage
    const uint32_t a_lm = (uint32_t)((warp_m * 32 + (lane & 7) + ((lane >> 3) & 1) * 8) * A_STR
                                     + (lane >> 4) * 8);
    const uint32_t b_lm = (uint32_t)(A_STAGE
                                     + (warp_n * 64 + (lane & 7) + (lane >> 4) * 8) * A_STR
                                     + ((lane >> 3) & 1) * 8);

    float acc[2][8][4];
#pragma unroll
    for (int mt = 0; mt < 2; mt++)
#pragma unroll
        for (int nt = 0; nt < 8; nt++)
#pragma unroll
            for (int r = 0; r < 4; r++) acc[mt][nt][r] = 0.f;

    // 256 rows (128 A + 128 B) x 128 B = 2048 x 16B chunks / 256 thr = 8 each
    auto prefetch = [&](int it, int buf) {
        const int k0 = it * 64;
#pragma unroll
        for (int cc = 0; cc < 8; cc++) {
            const int c = t + cc * 256;
            const int row = c >> 3, q = c & 7;       // chunk q -> halves q*8
            const __half* src = (row < 128)
                ? Ag + (size_t)(m0 + row) * HDIM + k0 + q * 8
                : Bg + (size_t)(n0 + row - 128) * HDIM + k0 + q * 8;
            const uint32_t dst = sbase + (uint32_t)(buf * STG + row * A_STR + q * 8) * 2u;
            CPA16(dst, src);
        }
        asm volatile("cp.async.commit_group;\n");
    };

    prefetch(0, 0);

    for (int it = 0; it < 8; ++it) {
        if (it < 7) prefetch(it + 1, (it + 1) & 1);
        else asm volatile("cp.async.commit_group;\n");
        asm volatile("cp.async.wait_group 1;\n");
        __syncthreads();

        const uint32_t stg = sbase + (uint32_t)((it & 1) * STG) * 2u;
#pragma unroll
        for (int ks = 0; ks < 4; ks++) {
            uint32_t af[2][4], bf[8][2];
#pragma unroll
            for (int mt = 0; mt < 2; mt++)
                ldsm_x4(af[mt], stg + (a_lm + mt * 16 * A_STR + ks * 16) * 2u);
#pragma unroll
            for (int ntp = 0; ntp < 4; ntp++) {
                uint32_t br[4];
                ldsm_x4(br, stg + (b_lm + ntp * 16 * A_STR + ks * 16) * 2u);
                bf[2 * ntp][0] = br[0]; bf[2 * ntp][1] = br[1];
                bf[2 * ntp + 1][0] = br[2]; bf[2 * ntp + 1][1] = br[3];
            }
#pragma unroll
            for (int mt = 0; mt < 2; mt++)
#pragma unroll
                for (int nt = 0; nt < 8; nt++)
                    mma_fp16(acc[mt][nt], af[mt], bf[nt]);
        }
        __syncthreads();
    }

    if (MODE == 0) {
        // tanh(acc + bias) -> g_h as fp16 (half2 stores)
#pragma unroll
        for (int mt = 0; mt < 2; mt++) {
            const int R = m0 + warp_m * 32 + mt * 16 + gr;
#pragma unroll
            for (int nt = 0; nt < 8; nt++) {
                const int C = n0 + warp_n * 64 + nt * 8 + tc * 2;
                const float b0 = bias[C], b1 = bias[C + 1];
                __half2 v0 = __floats2half2_rn(fast_tanh(acc[mt][nt][0] + b0),
                                               fast_tanh(acc[mt][nt][1] + b1));
                __half2 v1 = __floats2half2_rn(fast_tanh(acc[mt][nt][2] + b0),
                                               fast_tanh(acc[mt][nt][3] + b1));
                *(__half2*)&g_h[(size_t)R * HDIM + C] = v0;
                *(__half2*)&g_h[(size_t)(R + 8) * HDIM + C] = v1;
            }
        }
        return;
    }

    // ---- MODE 1: spline epilogue, two 64-row phases staged through smem ----
    float* U = (float*)sm;  // 64 x 132 floats = 33.8 KB (fits in dynamic smem)
    const int row = t & 63;
    const int gq = (t >> 6) * 2;   // 4 thread-groups x 2 h-groups = 8

#pragma unroll
    for (int p = 0; p < 2; p++) {
        __syncthreads();
        if ((warp_m >> 1) == p) {   // warps 2p, 2p+1 own rows [p*64, p*64+64)
#pragma unroll
            for (int mt = 0; mt < 2; mt++) {
                const int rl = (warp_m & 1) * 32 + mt * 16 + gr;
#pragma unroll
                for (int nt = 0; nt < 8; nt++) {
                    const int cl = warp_n * 64 + nt * 8 + tc * 2;
                    const float b0 = bias[n0 + cl], b1 = bias[n0 + cl + 1];
                    U[rl * 132 + cl] = fast_tanh(acc[mt][nt][0] + b0);
                    U[rl * 132 + cl + 1] = fast_tanh(acc[mt][nt][1] + b1);
                    U[(rl + 8) * 132 + cl] = fast_tanh(acc[mt][nt][2] + b0);
                    U[(rl + 8) * 132 + cl + 1] = fast_tanh(acc[mt][nt][3] + b1);
                }
            }
        }
        __syncthreads();

        const int grow = m0 + p * 64 + row;
        const int hbase = (n0 >> 4) + gq;
        float2 av = *(const float2*)&v_in[(size_t)grow * 1024 + 512 + hbase];
        float2 ov;
        float nlp = 0.f;
#pragma unroll
        for (int gg = 0; gg < 2; gg++) {
            const float a = (&av.x)[gg];
            const float tk = a * 16.0f;  // exact
            int k = (int)ceilf(tk) - 1;
            k = k < 0 ? 0 : (k > 15 ? 15 : k);
            const float4* up = (const float4*)&U[row * 132 + (gq + gg) * 16];
            float Z = 0.f, prefix = 0.f, sk = 0.f, uk = 0.f;
#pragma unroll
            for (int j4 = 0; j4 < 4; j4++) {
                float4 u4 = up[j4];
#pragma unroll
                for (int jj = 0; jj < 4; jj++) {
                    const int j = j4 * 4 + jj;
                    const float u = (&u4.x)[jj];
                    const float s = exp_poly(u);
                    Z += s;
                    prefix += (j < k) ? s : 0.f;
                    if (j == k) { sk = s; uk = u; }
                }
            }
            const float alpha = tk - (float)k;
            (&ov.x)[gg] = __fdividef(fmaf(alpha, sk, prefix), Z);
            nlp += __logf(Z) - uk;  // = -log p_k
        }
        *(float2*)&outp[(size_t)grow * 1024 + 512 + hbase] = ov;
        partial2[t] = nlp;
        __syncthreads();
        if (t < 64)
            g_partial[(size_t)(m0 + p * 64 + t) * NTILES_N + blockIdx.x] =
                partial2[t] + partial2[t + 64] + partial2[t + 128] + partial2[t + 192];
    }
}

// ---------------------------------------------------------------------------
// Prep kernels (destinations selected device-side)
// ---------------------------------------------------------------------------
// Fused: copy v_passive -> out[:, :512] AND write (v_passive - 0.5) as fp16
__global__ void k_prep_A(const float* __restrict__ v_in, float* __restrict__ out) {
    int i = blockIdx.x * 256 + threadIdx.x;  // over BATCH*128 float4
    int r = i >> 7, c4 = i & 127;
    float4 v = ((const float4*)v_in)[(size_t)r * 256 + c4];
    ((float4*)out)[(size_t)r * 256 + c4] = v;
    __half2 h0 = __floats2half2_rn(v.x - 0.5f, v.y - 0.5f);
    __half2 h1 = __floats2half2_rn(v.z - 0.5f, v.w - 0.5f);
    uint2 pk = make_uint2(*(uint32_t*)&h0, *(uint32_t*)&h1);
    ((uint2*)g_A1)[(size_t)r * 128 + c4] = pk;
}

// Tiled transpose to fp16: dst[n][k] = in[k][n]. WHICH selects destination.
template <int WHICH, int NCOLS>
__global__ void k_prep_WT(const float* __restrict__ in) {
    __half* __restrict__ outT = (WHICH == 0) ? g_W1T : g_W2T;
    __shared__ float tile[32][33];
    const int tx = threadIdx.x, ty = threadIdx.y;  // 32 x 8
    const int n0 = blockIdx.x * 32, k0 = blockIdx.y * 32;
#pragma unroll
    for (int i = 0; i < 4; i++)
        tile[ty + i * 8][tx] = in[(size_t)(k0 + ty + i * 8) * NCOLS + n0 + tx];
    __syncthreads();
#pragma unroll
    for (int i = 0; i < 4; i++)
        outT[(size_t)(n0 + ty + i * 8) * HDIM + k0 + tx] =
            __float2half_rn(tile[tx][ty + i * 8]);
}

// 2 threads per row + shfl combine
__global__ void k_reduce(const float* __restrict__ log_density,
                         float* __restrict__ out, int ld_offset) {
    int i = blockIdx.x * 256 + threadIdx.x;
    int r = i >> 1, h = i & 1;
    float s = 0.f;
    const float4* p4 = (const float4*)&g_partial[(size_t)r * NTILES_N + h * 32];
#pragma unroll
    for (int j = 0; j < 8; j++) {
        float4 v = p4[j];
        s += v.x + v.y + v.z + v.w;
    }
    s += __shfl_xor_sync(0xffffffffu, s, 1);
    if (!h) out[ld_offset + r] = s + log_density[r];
}

// ---------------------------------------------------------------------------
extern "C" void kernel_launch(void* const* d_in, const int* in_sizes, int n_in,
                              void* d_out, int out_size) {
    const float* v_in        = (const float*)d_in[0];
    const float* log_density = (const float*)d_in[1];
    const float* W1          = (const float*)d_in[2];
    const float* b1          = (const float*)d_in[3];
    const float* W2          = (const float*)d_in[4];
    const float* b2          = (const float*)d_in[5];
    float* out = (float*)d_out;
    const int ld_offset = out_size - BATCH;

    static bool attr_done = false;
    if (!attr_done) {
        cudaFuncSetAttribute(gemm_fp16<0>, cudaFuncAttributeMaxDynamicSharedMemorySize, SMEM_BYTES);
        cudaFuncSetAttribute(gemm_fp16<1>, cudaFuncAttributeMaxDynamicSharedMemorySize, SMEM_BYTES);
        cudaFuncSetAttribute(gemm_fp16<0>, cudaFuncAttributePreferredSharedMemoryCarveout,
                             cudaSharedmemCarveoutMaxShared);
        cudaFuncSetAttribute(gemm_fp16<1>, cudaFuncAttributePreferredSharedMemoryCarveout,
                             cudaSharedmemCarveoutMaxShared);
        attr_done = true;
    }

    k_prep_A<<<BATCH * 128 / 256, 256>>>(v_in, out);
    k_prep_WT<0, HDIM><<<dim3(HDIM / 32, HDIM / 32), dim3(32, 8)>>>(W1);
    k_prep_WT<1, NBIG><<<dim3(NBIG / 32, HDIM / 32), dim3(32, 8)>>>(W2);
    gemm_fp16<0><<<dim3(HDIM / 128, BATCH / 128), 256, SMEM_BYTES>>>(b1, v_in, out);
    gemm_fp16<1><<<dim3(NBIG / 128, BATCH / 128), 256, SMEM_BYTES>>>(b2, v_in, out);
    k_reduce<<<BATCH * 2 / 256, 256>>>(log_density, out, ld_offset);
}